// round 6
// baseline (speedup 1.0000x reference)
#include <cuda_runtime.h>
#include <math.h>

#define N_EDGES_C 1000000
#define TILE_E 64

// smem layout (floats), activation buffers feature-major [F][64]:
#define SMEM_FLOATS (64 * (192 + 128 + 64 + 32 + 16))
#define SMEM_BYTES (SMEM_FLOATS * 4)

typedef unsigned long long ull;

__device__ __forceinline__ ull pk2(float lo, float hi) {
    ull r; asm("mov.b64 %0, {%1, %2};" : "=l"(r) : "f"(lo), "f"(hi)); return r;
}
__device__ __forceinline__ void unpk2(ull v, float& lo, float& hi) {
    asm("mov.b64 {%0, %1}, %2;" : "=f"(lo), "=f"(hi) : "l"(v));
}
__device__ __forceinline__ ull ffma2(ull a, ull b, ull c) {
    ull d; asm("fma.rn.f32x2 %0, %1, %2, %3;" : "=l"(d) : "l"(a), "l"(b), "l"(c));
    return d;
}

// Packed fused layer: C[64][F_OUT] = act(A[64][F_IN] @ W[F_IN][F_OUT] + b).
// A (smem) feature-major [F_IN][64]. f32x2 lanes = 2 consecutive FEATURES
// (weights pair-load directly from row-major W; activation broadcast-packed
// once per edge per k). Thread tile: 2 consecutive edges x NF consecutive
// features; NF = F_OUT/8, NP = NF/2 f32x2 pairs. Warp spans all 64 edges,
// so the weight vector is warp-uniform (broadcast LDG).
template<int F_IN, int F_OUT, bool RELU, bool SMOUT, bool GOUT>
__device__ __forceinline__ void gemm_packed(
    const float* __restrict__ Asm, const float* __restrict__ W,
    const float* __restrict__ bias, float* __restrict__ Csm,
    float* __restrict__ gout, int tid)
{
    constexpr int NF = F_OUT / 8;
    constexpr int NP = NF / 2;
    const int e0 = (tid & 31) << 1;
    const int f0 = (tid >> 5) * NF;

    ull acc[NP][2];
#pragma unroll
    for (int p = 0; p < NP; ++p) {
        const float2 b2 = __ldg(reinterpret_cast<const float2*>(bias + f0) + p);
        const ull b = pk2(b2.x, b2.y);
        acc[p][0] = b; acc[p][1] = b;
    }

#pragma unroll 2
    for (int k = 0; k < F_IN; ++k) {
        const float2 av = *reinterpret_cast<const float2*>(Asm + k * TILE_E + e0);
        const ull a0 = pk2(av.x, av.x);
        const ull a1 = pk2(av.y, av.y);
        const float* wrow = W + k * F_OUT + f0;
        ull w[NP];
        if constexpr ((NP & 1) == 0) {
#pragma unroll
            for (int u = 0; u < NP / 2; ++u) {
                const ulonglong2 w2 =
                    __ldg(reinterpret_cast<const ulonglong2*>(wrow) + u);
                w[2 * u] = w2.x; w[2 * u + 1] = w2.y;
            }
        } else {  // NP == 1
            w[0] = __ldg(reinterpret_cast<const ull*>(wrow));
        }
#pragma unroll
        for (int p = 0; p < NP; ++p) {
            acc[p][0] = ffma2(a0, w[p], acc[p][0]);
            acc[p][1] = ffma2(a1, w[p], acc[p][1]);
        }
    }

    float vlo[NP][2], vhi[NP][2];
#pragma unroll
    for (int p = 0; p < NP; ++p) {
#pragma unroll
        for (int i = 0; i < 2; ++i) {
            unpk2(acc[p][i], vlo[p][i], vhi[p][i]);
            if constexpr (RELU) {
                vlo[p][i] = fmaxf(vlo[p][i], 0.0f);
                vhi[p][i] = fmaxf(vhi[p][i], 0.0f);
            }
        }
    }

    if constexpr (SMOUT) {
#pragma unroll
        for (int p = 0; p < NP; ++p) {
            *reinterpret_cast<float2*>(Csm + (f0 + 2 * p) * TILE_E + e0) =
                make_float2(vlo[p][0], vlo[p][1]);
            *reinterpret_cast<float2*>(Csm + (f0 + 2 * p + 1) * TILE_E + e0) =
                make_float2(vhi[p][0], vhi[p][1]);
        }
    }

    if constexpr (GOUT) {
#pragma unroll
        for (int i = 0; i < 2; ++i) {
            float* gp = gout + (size_t)(e0 + i) * F_OUT + f0;
            if constexpr ((NP & 1) == 0) {
#pragma unroll
                for (int u = 0; u < NP / 2; ++u)
                    *reinterpret_cast<float4*>(gp + 4 * u) =
                        make_float4(vlo[2*u][i], vhi[2*u][i],
                                    vlo[2*u+1][i], vhi[2*u+1][i]);
            } else {
                *reinterpret_cast<float2*>(gp) = make_float2(vlo[0][i], vhi[0][i]);
            }
        }
    }
}

__global__ void __launch_bounds__(256, 2)
gnn_fused_kernel(
    const float* __restrict__ x,
    const float* __restrict__ ea,
    const int* __restrict__ ei,     // int32 (jax default, no x64)
    const float* __restrict__ W_e1, const float* __restrict__ b_e1,
    const float* __restrict__ W_e2, const float* __restrict__ b_e2,
    const float* __restrict__ W_e3, const float* __restrict__ b_e3,
    const float* __restrict__ W_d1, const float* __restrict__ b_d1,
    const float* __restrict__ W_d2, const float* __restrict__ b_d2,
    const float* __restrict__ W_d3, const float* __restrict__ b_d3,
    const float* __restrict__ W_s1, const float* __restrict__ b_s1,
    const float* __restrict__ W_s2, const float* __restrict__ b_s2,
    float* __restrict__ enc_out,    // [E,32]
    float* __restrict__ rec_out,    // [E,192]
    float* __restrict__ trip_out,   // [E,192]
    float* __restrict__ score_out)  // [E,1]
{
    extern __shared__ float smem[];
    float* Tsm   = smem;                 // [192][64]
    float* Asm   = Tsm + 192 * TILE_E;   // [128][64]
    float* Bsm   = Asm + 128 * TILE_E;   // [64][64]
    float* ENCsm = Bsm + 64 * TILE_E;    // [32][64]
    float* S1sm  = ENCsm + 32 * TILE_E;  // [16][64]

    const int tid = threadIdx.x;
    const long long ebase = (long long)blockIdx.x * TILE_E;

    // ---- Gather: triplets = [x[src] | edge_attr | x[dst]] -> smem (feature-major)
    //      and streamed straight to trip_out (row-major).
    {
        const int el = tid >> 2;   // 0..63 edge within tile
        const int r  = tid & 3;    // 4 threads per edge, 12 float4 each
        const long long eg = ebase + el;
        const int s = __ldg(ei + eg);
        const int d = __ldg(ei + N_EDGES_C + eg);
        const float4* srcp = reinterpret_cast<const float4*>(x + (size_t)s * 64);
        const float4* eap  = reinterpret_cast<const float4*>(ea + (size_t)eg * 64);
        const float4* dstp = reinterpret_cast<const float4*>(x + (size_t)d * 64);
        float* top = trip_out + (size_t)eg * 192;
#pragma unroll
        for (int m = 0; m < 12; ++m) {
            const int q = r * 12 + m;  // float4 index in [0,48)
            float4 v;
            if (q < 16)      v = __ldg(srcp + q);
            else if (q < 32) v = __ldg(eap + (q - 16));
            else             v = __ldg(dstp + (q - 32));
            const int k = q * 4;
            Tsm[(k + 0) * TILE_E + el] = v.x;
            Tsm[(k + 1) * TILE_E + el] = v.y;
            Tsm[(k + 2) * TILE_E + el] = v.z;
            Tsm[(k + 3) * TILE_E + el] = v.w;
            *reinterpret_cast<float4*>(top + k) = v;
        }
    }
    __syncthreads();

    // ---- Encoder
    gemm_packed<192, 128, true,  true,  false>(Tsm, W_e1, b_e1, Asm, nullptr, tid);
    __syncthreads();
    gemm_packed<128, 64,  true,  true,  false>(Asm, W_e2, b_e2, Bsm, nullptr, tid);
    __syncthreads();
    gemm_packed<64,  32,  false, true,  true >(Bsm, W_e3, b_e3, ENCsm,
                                               enc_out + ebase * 32, tid);
    __syncthreads();

    // ---- Decoder
    gemm_packed<32,  64,  true,  true,  false>(ENCsm, W_d1, b_d1, Bsm, nullptr, tid);
    __syncthreads();
    gemm_packed<64,  128, true,  true,  false>(Bsm, W_d2, b_d2, Asm, nullptr, tid);
    __syncthreads();
    gemm_packed<128, 192, false, false, true >(Asm, W_d3, b_d3, nullptr,
                                               rec_out + ebase * 192, tid);

    // ---- Scorer hidden (touches only ENC/S1, disjoint from d3's A reads)
    gemm_packed<32,  16,  true,  true,  false>(ENCsm, W_s1, b_s1, S1sm, nullptr, tid);
    __syncthreads();

    // ---- Scorer output: sigmoid(S1 @ W_s2 + b_s2)
    if (tid < TILE_E) {
        float acc = __ldg(b_s2);
#pragma unroll
        for (int k = 0; k < 16; ++k)
            acc += S1sm[k * TILE_E + tid] * __ldg(W_s2 + k);
        score_out[ebase + tid] = 1.0f / (1.0f + expf(-acc));
    }
}

extern "C" void kernel_launch(void* const* d_in, const int* in_sizes, int n_in,
                              void* d_out, int out_size)
{
    const float* x   = (const float*)d_in[0];
    const float* ea  = (const float*)d_in[1];
    const int*   ei  = (const int*)d_in[2];
    const float* W_e1 = (const float*)d_in[3];  const float* b_e1 = (const float*)d_in[4];
    const float* W_e2 = (const float*)d_in[5];  const float* b_e2 = (const float*)d_in[6];
    const float* W_e3 = (const float*)d_in[7];  const float* b_e3 = (const float*)d_in[8];
    const float* W_d1 = (const float*)d_in[9];  const float* b_d1 = (const float*)d_in[10];
    const float* W_d2 = (const float*)d_in[11]; const float* b_d2 = (const float*)d_in[12];
    const float* W_d3 = (const float*)d_in[13]; const float* b_d3 = (const float*)d_in[14];
    const float* W_s1 = (const float*)d_in[15]; const float* b_s1 = (const float*)d_in[16];
    const float* W_s2 = (const float*)d_in[17]; const float* b_s2 = (const float*)d_in[18];

    float* out = (float*)d_out;
    // Output layout: encoded [E,32] | reconstructed [E,192] | triplets [E,192] | scores [E,1]
    float* enc_out   = out;
    float* rec_out   = out + 32LL  * N_EDGES_C;
    float* trip_out  = out + 224LL * N_EDGES_C;
    float* score_out = out + 416LL * N_EDGES_C;

    cudaFuncSetAttribute(gnn_fused_kernel,
                         cudaFuncAttributeMaxDynamicSharedMemorySize, SMEM_BYTES);

    const int n_tiles = N_EDGES_C / TILE_E;  // 15625
    gnn_fused_kernel<<<n_tiles, 256, SMEM_BYTES>>>(
        x, ea, ei,
        W_e1, b_e1, W_e2, b_e2, W_e3, b_e3,
        W_d1, b_d1, W_d2, b_d2, W_d3, b_d3,
        W_s1, b_s1, W_s2, b_s2,
        enc_out, rec_out, trip_out, score_out);
}

// round 10
// speedup vs baseline: 1.0697x; 1.0697x over previous
#include <cuda_runtime.h>
#include <math.h>

#define N_EDGES_C 1000000
#define TILE_E 64

// Aliased smem layout (floats):
//   Region A : [128][64] = 8192   (h1 / r2)         offset 0
//   Region T : [192][64] = 12288  (triplets)        offset 8192
//     after e1, T is reused:  B   [64][64] = 4096   at T+0
//                             ENC [32][64] = 2048   at T+4096
//                             S1  [16][64] = 1024   at T+6144
#define SMEM_FLOATS (8192 + 12288)
#define SMEM_BYTES (SMEM_FLOATS * 4)

// Fused layer: C[64][F_OUT] = act(A[64][F_IN] @ W[F_IN][F_OUT] + b)
// Asm feature-major [F_IN][64]. Thread tile: 2 consecutive edges x NF
// consecutive features, NF = F_OUT/8. f0 = warp_id*NF -> the weight row
// segment is warp-uniform (broadcast LDG, L1-cached). Activation load is
// one LDS.64 per k (8x redundancy across the 8 warp f-groups).
template<int F_IN, int F_OUT, bool RELU, bool SMOUT, bool GOUT>
__device__ __forceinline__ void gemm_layer(
    const float* __restrict__ Asm, const float* __restrict__ W,
    const float* __restrict__ bias, float* __restrict__ Csm,
    float* __restrict__ gout, int tid)
{
    constexpr int NF = F_OUT / 8;
    const int e0 = (tid & 31) << 1;     // 2 consecutive edges
    const int f0 = (tid >> 5) * NF;     // warp-uniform feature base

    float acc[NF][2];
#pragma unroll
    for (int j = 0; j < NF; ++j) {
        const float b = __ldg(bias + f0 + j);
        acc[j][0] = b; acc[j][1] = b;
    }

#pragma unroll 2
    for (int k = 0; k < F_IN; ++k) {
        const float2 av = *reinterpret_cast<const float2*>(Asm + k * TILE_E + e0);
        const float* wr = W + k * F_OUT + f0;
        if constexpr ((NF & 3) == 0) {
#pragma unroll
            for (int u = 0; u < NF / 4; ++u) {
                const float4 w4 = __ldg(reinterpret_cast<const float4*>(wr) + u);
                acc[4*u+0][0] += av.x * w4.x; acc[4*u+0][1] += av.y * w4.x;
                acc[4*u+1][0] += av.x * w4.y; acc[4*u+1][1] += av.y * w4.y;
                acc[4*u+2][0] += av.x * w4.z; acc[4*u+2][1] += av.y * w4.z;
                acc[4*u+3][0] += av.x * w4.w; acc[4*u+3][1] += av.y * w4.w;
            }
        } else {  // NF == 2 (scorer hidden)
            const float2 w2 = __ldg(reinterpret_cast<const float2*>(wr));
            acc[0][0] += av.x * w2.x; acc[0][1] += av.y * w2.x;
            acc[1][0] += av.x * w2.y; acc[1][1] += av.y * w2.y;
        }
    }

    if constexpr (RELU) {
#pragma unroll
        for (int j = 0; j < NF; ++j) {
            acc[j][0] = fmaxf(acc[j][0], 0.0f);
            acc[j][1] = fmaxf(acc[j][1], 0.0f);
        }
    }

    if constexpr (SMOUT) {
#pragma unroll
        for (int j = 0; j < NF; ++j)
            *reinterpret_cast<float2*>(Csm + (f0 + j) * TILE_E + e0) =
                make_float2(acc[j][0], acc[j][1]);
    }

    if constexpr (GOUT) {
#pragma unroll
        for (int i = 0; i < 2; ++i) {
            float* gp = gout + (size_t)(e0 + i) * F_OUT + f0;
            if constexpr ((NF & 3) == 0) {
#pragma unroll
                for (int u = 0; u < NF / 4; ++u)
                    *reinterpret_cast<float4*>(gp + 4 * u) =
                        make_float4(acc[4*u+0][i], acc[4*u+1][i],
                                    acc[4*u+2][i], acc[4*u+3][i]);
            } else {
                *reinterpret_cast<float2*>(gp) = make_float2(acc[0][i], acc[1][i]);
            }
        }
    }
}

__global__ void __launch_bounds__(256, 2)
gnn_fused_kernel(
    const float* __restrict__ x,
    const float* __restrict__ ea,
    const int* __restrict__ ei,     // int32 (jax default, no x64)
    const float* __restrict__ W_e1, const float* __restrict__ b_e1,
    const float* __restrict__ W_e2, const float* __restrict__ b_e2,
    const float* __restrict__ W_e3, const float* __restrict__ b_e3,
    const float* __restrict__ W_d1, const float* __restrict__ b_d1,
    const float* __restrict__ W_d2, const float* __restrict__ b_d2,
    const float* __restrict__ W_d3, const float* __restrict__ b_d3,
    const float* __restrict__ W_s1, const float* __restrict__ b_s1,
    const float* __restrict__ W_s2, const float* __restrict__ b_s2,
    float* __restrict__ enc_out,    // [E,32]
    float* __restrict__ rec_out,    // [E,192]
    float* __restrict__ trip_out,   // [E,192]
    float* __restrict__ score_out)  // [E,1]
{
    extern __shared__ float smem[];
    float* Asm   = smem;                 // [128][64]
    float* Tsm   = smem + 128 * TILE_E;  // [192][64]; aliased after e1:
    float* Bsm   = Tsm;                  //   [64][64]
    float* ENCsm = Tsm + 64 * TILE_E;    //   [32][64]
    float* S1sm  = Tsm + 96 * TILE_E;    //   [16][64]

    const int tid = threadIdx.x;
    const long long ebase = (long long)blockIdx.x * TILE_E;

    // ---- Gather: triplets = [x[src] | edge_attr | x[dst]] -> smem (feature-major)
    //      and streamed straight to trip_out (row-major).
    {
        const int el = tid >> 2;   // 0..63 edge within tile
        const int r  = tid & 3;    // 4 threads per edge, 12 float4 each
        const long long eg = ebase + el;
        const int s = __ldg(ei + eg);
        const int d = __ldg(ei + N_EDGES_C + eg);
        const float4* srcp = reinterpret_cast<const float4*>(x + (size_t)s * 64);
        const float4* eap  = reinterpret_cast<const float4*>(ea + (size_t)eg * 64);
        const float4* dstp = reinterpret_cast<const float4*>(x + (size_t)d * 64);
        float* top = trip_out + (size_t)eg * 192;
#pragma unroll
        for (int m = 0; m < 12; ++m) {
            const int q = r * 12 + m;  // float4 index in [0,48)
            float4 v;
            if (q < 16)      v = __ldg(srcp + q);
            else if (q < 32) v = __ldg(eap + (q - 16));
            else             v = __ldg(dstp + (q - 32));
            const int k = q * 4;
            Tsm[(k + 0) * TILE_E + el] = v.x;
            Tsm[(k + 1) * TILE_E + el] = v.y;
            Tsm[(k + 2) * TILE_E + el] = v.z;
            Tsm[(k + 3) * TILE_E + el] = v.w;
            *reinterpret_cast<float4*>(top + k) = v;
        }
    }
    __syncthreads();

    // ---- Encoder
    gemm_layer<192, 128, true,  true,  false>(Tsm, W_e1, b_e1, Asm, nullptr, tid);
    __syncthreads();   // T dead from here; B/ENC/S1 alias into it
    gemm_layer<128, 64,  true,  true,  false>(Asm, W_e2, b_e2, Bsm, nullptr, tid);
    __syncthreads();
    gemm_layer<64,  32,  false, true,  true >(Bsm, W_e3, b_e3, ENCsm,
                                              enc_out + ebase * 32, tid);
    __syncthreads();

    // ---- Decoder (d1 writes over B region; ENC stays intact)
    gemm_layer<32,  64,  true,  true,  false>(ENCsm, W_d1, b_d1, Bsm, nullptr, tid);
    __syncthreads();
    gemm_layer<64,  128, true,  true,  false>(Bsm, W_d2, b_d2, Asm, nullptr, tid);
    __syncthreads();
    gemm_layer<128, 192, false, false, true >(Asm, W_d3, b_d3, nullptr,
                                              rec_out + ebase * 192, tid);

    // ---- Scorer hidden (reads ENC, writes S1; disjoint from d3's A reads)
    gemm_layer<32,  16,  true,  true,  false>(ENCsm, W_s1, b_s1, S1sm, nullptr, tid);
    __syncthreads();

    // ---- Scorer output: sigmoid(S1 @ W_s2 + b_s2)
    if (tid < TILE_E) {
        float acc = __ldg(b_s2);
#pragma unroll
        for (int k = 0; k < 16; ++k)
            acc += S1sm[k * TILE_E + tid] * __ldg(W_s2 + k);
        score_out[ebase + tid] = 1.0f / (1.0f + expf(-acc));
    }
}

extern "C" void kernel_launch(void* const* d_in, const int* in_sizes, int n_in,
                              void* d_out, int out_size)
{
    const float* x   = (const float*)d_in[0];
    const float* ea  = (const float*)d_in[1];
    const int*   ei  = (const int*)d_in[2];
    const float* W_e1 = (const float*)d_in[3];  const float* b_e1 = (const float*)d_in[4];
    const float* W_e2 = (const float*)d_in[5];  const float* b_e2 = (const float*)d_in[6];
    const float* W_e3 = (const float*)d_in[7];  const float* b_e3 = (const float*)d_in[8];
    const float* W_d1 = (const float*)d_in[9];  const float* b_d1 = (const float*)d_in[10];
    const float* W_d2 = (const float*)d_in[11]; const float* b_d2 = (const float*)d_in[12];
    const float* W_d3 = (const float*)d_in[13]; const float* b_d3 = (const float*)d_in[14];
    const float* W_s1 = (const float*)d_in[15]; const float* b_s1 = (const float*)d_in[16];
    const float* W_s2 = (const float*)d_in[17]; const float* b_s2 = (const float*)d_in[18];

    float* out = (float*)d_out;
    // Output layout: encoded [E,32] | reconstructed [E,192] | triplets [E,192] | scores [E,1]
    float* enc_out   = out;
    float* rec_out   = out + 32LL  * N_EDGES_C;
    float* trip_out  = out + 224LL * N_EDGES_C;
    float* score_out = out + 416LL * N_EDGES_C;

    cudaFuncSetAttribute(gnn_fused_kernel,
                         cudaFuncAttributeMaxDynamicSharedMemorySize, SMEM_BYTES);

    const int n_tiles = N_EDGES_C / TILE_E;  // 15625
    gnn_fused_kernel<<<n_tiles, 256, SMEM_BYTES>>>(
        x, ea, ei,
        W_e1, b_e1, W_e2, b_e2, W_e3, b_e3,
        W_d1, b_d1, W_d2, b_d2, W_d3, b_d3,
        W_s1, b_s1, W_s2, b_s2,
        enc_out, rec_out, trip_out, score_out);
}

// round 15
// speedup vs baseline: 1.4683x; 1.3726x over previous
#include <cuda_runtime.h>
#include <math.h>

#define N_EDGES_C 1000000
#define TILE_E 64

// Aliased smem layout (floats), feature-major [F][64]:
//   A : [128][64] = 8192 floats (32KB)   offset 0        (h1 / r2)
//   T : [192][64] = 12288 floats (48KB)  offset 8192     (triplets)
//     after e1, T is reused:  B   [64][64] at T+0        (h2 / r1)
//                             ENC [32][64] at T+4096     (alive to the end)
// Total 80KB/CTA -> 2 CTAs = 160KB smem -> ~68KB L1D carveout for weights.
#define SMEM_FLOATS (8192 + 12288)
#define SMEM_BYTES (SMEM_FLOATS * 4)

// Fused layer: C[64][F_OUT] = act(A[64][F_IN] @ W[F_IN][F_OUT] + b)
// Asm feature-major [F_IN][64]. Thread tile: 4 consecutive edges x NF
// consecutive features (NF = F_OUT/16).  (R4 mapping — fastest measured.)
template<int F_IN, int F_OUT, bool RELU, bool SMOUT, bool GOUT>
__device__ __forceinline__ void gemm_layer(
    const float* __restrict__ Asm, const float* __restrict__ W,
    const float* __restrict__ bias, float* __restrict__ Csm,
    float* __restrict__ gout, int tid)
{
    constexpr int NF = F_OUT / 16;
    const int e0 = (tid & 15) << 2;
    const int f0 = (tid >> 4) * NF;

    float acc[NF][4];
#pragma unroll
    for (int j = 0; j < NF; ++j) {
        const float b = __ldg(bias + f0 + j);
        acc[j][0] = b; acc[j][1] = b; acc[j][2] = b; acc[j][3] = b;
    }

#pragma unroll 4
    for (int k = 0; k < F_IN; ++k) {
        const float4 av = *reinterpret_cast<const float4*>(Asm + k * TILE_E + e0);
        const float* wr = W + k * F_OUT + f0;
        if constexpr ((NF & 3) == 0) {
#pragma unroll
            for (int u = 0; u < NF / 4; ++u) {
                const float4 w4 = __ldg(reinterpret_cast<const float4*>(wr) + u);
                acc[4*u+0][0] += av.x * w4.x; acc[4*u+0][1] += av.y * w4.x;
                acc[4*u+0][2] += av.z * w4.x; acc[4*u+0][3] += av.w * w4.x;
                acc[4*u+1][0] += av.x * w4.y; acc[4*u+1][1] += av.y * w4.y;
                acc[4*u+1][2] += av.z * w4.y; acc[4*u+1][3] += av.w * w4.y;
                acc[4*u+2][0] += av.x * w4.z; acc[4*u+2][1] += av.y * w4.z;
                acc[4*u+2][2] += av.z * w4.z; acc[4*u+2][3] += av.w * w4.z;
                acc[4*u+3][0] += av.x * w4.w; acc[4*u+3][1] += av.y * w4.w;
                acc[4*u+3][2] += av.z * w4.w; acc[4*u+3][3] += av.w * w4.w;
            }
        } else {  // NF == 2 (e3)
            const float2 w2 = __ldg(reinterpret_cast<const float2*>(wr));
            acc[0][0] += av.x * w2.x; acc[0][1] += av.y * w2.x;
            acc[0][2] += av.z * w2.x; acc[0][3] += av.w * w2.x;
            acc[1][0] += av.x * w2.y; acc[1][1] += av.y * w2.y;
            acc[1][2] += av.z * w2.y; acc[1][3] += av.w * w2.y;
        }
    }

    if constexpr (RELU) {
#pragma unroll
        for (int j = 0; j < NF; ++j)
#pragma unroll
            for (int i = 0; i < 4; ++i)
                acc[j][i] = fmaxf(acc[j][i], 0.0f);
    }

    if constexpr (SMOUT) {
#pragma unroll
        for (int j = 0; j < NF; ++j)
            *reinterpret_cast<float4*>(Csm + (f0 + j) * TILE_E + e0) =
                make_float4(acc[j][0], acc[j][1], acc[j][2], acc[j][3]);
    }

    if constexpr (GOUT) {
#pragma unroll
        for (int i = 0; i < 4; ++i) {
            float* gp = gout + (size_t)(e0 + i) * F_OUT + f0;
            if constexpr ((NF & 3) == 0) {
#pragma unroll
                for (int u = 0; u < NF / 4; ++u)
                    *reinterpret_cast<float4*>(gp + 4 * u) =
                        make_float4(acc[4*u+0][i], acc[4*u+1][i],
                                    acc[4*u+2][i], acc[4*u+3][i]);
            } else {
                *reinterpret_cast<float2*>(gp) = make_float2(acc[0][i], acc[1][i]);
            }
        }
    }
}

__global__ void __launch_bounds__(256, 2)
gnn_fused_kernel(
    const float* __restrict__ x,
    const float* __restrict__ ea,
    const int* __restrict__ ei,     // int32 (jax default, no x64)
    const float* __restrict__ W_e1, const float* __restrict__ b_e1,
    const float* __restrict__ W_e2, const float* __restrict__ b_e2,
    const float* __restrict__ W_e3, const float* __restrict__ b_e3,
    const float* __restrict__ W_d1, const float* __restrict__ b_d1,
    const float* __restrict__ W_d2, const float* __restrict__ b_d2,
    const float* __restrict__ W_d3, const float* __restrict__ b_d3,
    const float* __restrict__ W_s1, const float* __restrict__ b_s1,
    const float* __restrict__ W_s2, const float* __restrict__ b_s2,
    float* __restrict__ enc_out,    // [E,32]
    float* __restrict__ rec_out,    // [E,192]
    float* __restrict__ trip_out,   // [E,192]
    float* __restrict__ score_out)  // [E,1]
{
    extern __shared__ float smem[];
    float* Asm   = smem;                 // [128][64]
    float* Tsm   = smem + 128 * TILE_E;  // [192][64]; aliased after e1:
    float* Bsm   = Tsm;                  //   [64][64]
    float* ENCsm = Tsm + 64 * TILE_E;    //   [32][64]  (alive to kernel end)

    const int tid = threadIdx.x;
    const long long ebase = (long long)blockIdx.x * TILE_E;

    // ---- Gather: triplets = [x[src] | edge_attr | x[dst]] -> smem (feature-major)
    //      and streamed straight to trip_out (row-major).
    {
        const int el = tid >> 2;   // 0..63 edge within tile
        const int r  = tid & 3;    // 4 threads per edge, 12 float4 each
        const long long eg = ebase + el;
        const int s = __ldg(ei + eg);
        const int d = __ldg(ei + N_EDGES_C + eg);
        const float4* srcp = reinterpret_cast<const float4*>(x + (size_t)s * 64);
        const float4* eap  = reinterpret_cast<const float4*>(ea + (size_t)eg * 64);
        const float4* dstp = reinterpret_cast<const float4*>(x + (size_t)d * 64);
        float* top = trip_out + (size_t)eg * 192;
#pragma unroll
        for (int m = 0; m < 12; ++m) {
            const int q = r * 12 + m;  // float4 index in [0,48)
            float4 v;
            if (q < 16)      v = __ldg(srcp + q);
            else if (q < 32) v = __ldg(eap + (q - 16));
            else             v = __ldg(dstp + (q - 32));
            const int k = q * 4;
            Tsm[(k + 0) * TILE_E + el] = v.x;
            Tsm[(k + 1) * TILE_E + el] = v.y;
            Tsm[(k + 2) * TILE_E + el] = v.z;
            Tsm[(k + 3) * TILE_E + el] = v.w;
            *reinterpret_cast<float4*>(top + k) = v;
        }
    }
    __syncthreads();

    // ---- Encoder
    gemm_layer<192, 128, true,  true,  false>(Tsm, W_e1, b_e1, Asm, nullptr, tid);
    __syncthreads();   // T dead from here; B/ENC alias into it
    gemm_layer<128, 64,  true,  true,  false>(Asm, W_e2, b_e2, Bsm, nullptr, tid);
    __syncthreads();
    gemm_layer<64,  32,  false, true,  true >(Bsm, W_e3, b_e3, ENCsm,
                                              enc_out + ebase * 32, tid);
    __syncthreads();

    // ---- Decoder (d1 overwrites B region; ENC stays intact)
    gemm_layer<32,  64,  true,  true,  false>(ENCsm, W_d1, b_d1, Bsm, nullptr, tid);
    __syncthreads();
    gemm_layer<64,  128, true,  true,  false>(Bsm, W_d2, b_d2, Asm, nullptr, tid);
    __syncthreads();
    gemm_layer<128, 192, false, false, true >(Asm, W_d3, b_d3, nullptr,
                                              rec_out + ebase * 192, tid);

    // ---- Scorer: both layers in registers straight from ENC (no smem buffer,
    //      no extra barriers: ENC untouched since e3, d1 only wrote B region).
    if (tid < TILE_E) {
        float e[32];
#pragma unroll
        for (int k = 0; k < 32; ++k)
            e[k] = ENCsm[k * TILE_E + tid];
        float acc = __ldg(b_s2);
#pragma unroll
        for (int j = 0; j < 16; ++j) {
            float hs = __ldg(b_s1 + j);
#pragma unroll
            for (int k = 0; k < 32; ++k)
                hs += e[k] * __ldg(W_s1 + k * 16 + j);
            hs = fmaxf(hs, 0.0f);
            acc += hs * __ldg(W_s2 + j);
        }
        score_out[ebase + tid] = 1.0f / (1.0f + expf(-acc));
    }
}

extern "C" void kernel_launch(void* const* d_in, const int* in_sizes, int n_in,
                              void* d_out, int out_size)
{
    const float* x   = (const float*)d_in[0];
    const float* ea  = (const float*)d_in[1];
    const int*   ei  = (const int*)d_in[2];
    const float* W_e1 = (const float*)d_in[3];  const float* b_e1 = (const float*)d_in[4];
    const float* W_e2 = (const float*)d_in[5];  const float* b_e2 = (const float*)d_in[6];
    const float* W_e3 = (const float*)d_in[7];  const float* b_e3 = (const float*)d_in[8];
    const float* W_d1 = (const float*)d_in[9];  const float* b_d1 = (const float*)d_in[10];
    const float* W_d2 = (const float*)d_in[11]; const float* b_d2 = (const float*)d_in[12];
    const float* W_d3 = (const float*)d_in[13]; const float* b_d3 = (const float*)d_in[14];
    const float* W_s1 = (const float*)d_in[15]; const float* b_s1 = (const float*)d_in[16];
    const float* W_s2 = (const float*)d_in[17]; const float* b_s2 = (const float*)d_in[18];

    float* out = (float*)d_out;
    // Output layout: encoded [E,32] | reconstructed [E,192] | triplets [E,192] | scores [E,1]
    float* enc_out   = out;
    float* rec_out   = out + 32LL  * N_EDGES_C;
    float* trip_out  = out + 224LL * N_EDGES_C;
    float* score_out = out + 416LL * N_EDGES_C;

    cudaFuncSetAttribute(gnn_fused_kernel,
                         cudaFuncAttributeMaxDynamicSharedMemorySize, SMEM_BYTES);

    const int n_tiles = N_EDGES_C / TILE_E;  // 15625
    gnn_fused_kernel<<<n_tiles, 256, SMEM_BYTES>>>(
        x, ea, ei,
        W_e1, b_e1, W_e2, b_e2, W_e3, b_e3,
        W_d1, b_d1, W_d2, b_d2, W_d3, b_d3,
        W_s1, b_s1, W_s2, b_s2,
        enc_out, rec_out, trip_out, score_out);
}